// round 5
// baseline (speedup 1.0000x reference)
#include <cuda_runtime.h>
#include <math.h>

#define TT   128
#define BB   512
#define HH   128
#define EMBD 300
#define DD   256
#define G3   384
#define EPSF 1e-7f

typedef unsigned long long ull;

__device__ float g_xp_f[TT * BB * G3];
__device__ float g_xp_b[TT * BB * G3];
__device__ float g_ys_f[TT * BB * HH];
__device__ float g_ys_b[TT * BB * HH];
__device__ float g_hyp[TT * BB * DD];
__device__ float g_scores[TT * BB];
__device__ float g_rr2[TT * BB];

// packed fp32x2 FMA: d.lo += a.lo*b.lo ; d.hi += a.hi*b.hi (single issue slot)
__device__ __forceinline__ void dfma(ull& d, ull a, ull b) {
    asm("fma.rn.f32x2 %0, %1, %2, %0;" : "+l"(d) : "l"(a), "l"(b));
}
__device__ __forceinline__ float dsum(ull v) {
    unsigned lo = (unsigned)v, hi = (unsigned)(v >> 32);
    return __uint_as_float(lo) + __uint_as_float(hi);
}

// ============================================================
// K1: embed gather + input projections. M=65536,N=768,K=300
// smem tiles stored k-pair-interleaved: [k/2][row] float2
// xT2: 150 rows x 70 float2 (140 floats) ; Ws2: 50 rows x 134 float2
// ============================================================
#define X1_ROW 140   // floats per kk row of xT2 (64 rows*2 + pad)
#define W1_ROW 268   // floats per kk row of Ws2 (128 cols*2 + pad)
#define X1_FLOATS (150 * X1_ROW)

__global__ __launch_bounds__(256) void k1_inproj(
    const int* __restrict__ tokens, const float* __restrict__ emb,
    const float* __restrict__ Wf, const float* __restrict__ bfv,
    const float* __restrict__ Wb, const float* __restrict__ bbv)
{
    extern __shared__ float sm[];
    float* xTf = sm;                    // [150][X1_ROW]
    float* Wsf = sm + X1_FLOATS;        // [50][W1_ROW]
    __shared__ int tk[64];

    const int tid  = threadIdx.x;
    const int row0 = blockIdx.x * 64;
    const int t    = row0 >> 9;
    const int b0   = row0 & 511;
    const int coff = blockIdx.y * 128;

    if (tid < 64) tk[tid] = tokens[row0 + tid];
    __syncthreads();

    // gather embeddings -> k-pair layout
    {
        const int rg = tid >> 5, lane = tid & 31;
        for (int r = rg; r < 64; r += 8) {
            const float* e = emb + (long long)tk[r] * EMBD;
            for (int k = lane; k < EMBD; k += 32)
                xTf[(k >> 1) * X1_ROW + r * 2 + (k & 1)] = e[k];
        }
    }

    const bool fwd = (coff < G3);
    const float* Wsrc = fwd ? Wf : Wb;
    const float* bsrc = fwd ? bfv : bbv;
    const int cbase = fwd ? coff : (coff - G3);

    ull acc2[4][8];
    #pragma unroll
    for (int i = 0; i < 4; i++)
        #pragma unroll
        for (int j = 0; j < 8; j++) acc2[i][j] = 0ull;

    const int tr = tid >> 4, tc = tid & 15;
    const ull* xTu = (const ull*)sm;                          // 70 ull per kk row
    const ulonglong2* Wsu = (const ulonglong2*)(sm + X1_FLOATS); // 67 ull2 per kk row

    for (int kc = 0; kc < 3; kc++) {
        __syncthreads();
        {   // stage W chunk (K=100) into k-pair layout
            const int cg = tid >> 5, lane = tid & 31;
            for (int c = cg; c < 128; c += 8) {
                const float* wrow = Wsrc + (long long)(cbase + c) * EMBD + kc * 100;
                for (int k = lane; k < 100; k += 32)
                    Wsf[(k >> 1) * W1_ROW + c * 2 + (k & 1)] = wrow[k];
            }
        }
        __syncthreads();
        #pragma unroll 2
        for (int kk = 0; kk < 50; kk++) {
            ull av[4];
            const ull* xr = xTu + (kc * 50 + kk) * (X1_ROW / 2) + tr * 4;
            #pragma unroll
            for (int i = 0; i < 4; i++) av[i] = xr[i];
            ulonglong2 w0 = Wsu[kk * (W1_ROW / 4) + tc * 2];
            ulonglong2 w1 = Wsu[kk * (W1_ROW / 4) + tc * 2 + 1];
            ulonglong2 w2 = Wsu[kk * (W1_ROW / 4) + 32 + tc * 2];
            ulonglong2 w3 = Wsu[kk * (W1_ROW / 4) + 32 + tc * 2 + 1];
            ull wv[8] = {w0.x, w0.y, w1.x, w1.y, w2.x, w2.y, w3.x, w3.y};
            #pragma unroll
            for (int i = 0; i < 4; i++)
                #pragma unroll
                for (int j = 0; j < 8; j++)
                    dfma(acc2[i][j], av[i], wv[j]);
        }
    }

    #pragma unroll
    for (int j = 0; j < 8; j++) {
        const int c = (j < 4) ? (tc * 4 + j) : (64 + tc * 4 + (j - 4));
        const float bv = bsrc[cbase + c];
        #pragma unroll
        for (int i = 0; i < 4; i++) {
            const int b = b0 + tr * 4 + i;
            const float v = dsum(acc2[i][j]) + bv;
            if (fwd)
                g_xp_f[((long long)t * BB + b) * G3 + cbase + c] = v;
            else
                g_xp_b[((long long)(TT - 1 - t) * BB + b) * G3 + cbase + c] = v;
        }
    }
}

// ============================================================
// K2: GRU scan. 128 blocks x 384 thr; thread j owns W_hh row j.
// dot products via FFMA2 (even/odd k lanes), horizontal add at end.
// ============================================================
__global__ __launch_bounds__(384, 1) void k2_scan(
    const float* __restrict__ hidden,
    const float* __restrict__ Whh_f, const float* __restrict__ bhh_f,
    const float* __restrict__ Whh_b, const float* __restrict__ bhh_b)
{
    __shared__ __align__(16) float hs[8 * 128];
    __shared__ float sg[256 * 9];

    const int tid = threadIdx.x;
    const int dir = blockIdx.x >> 6;
    const int b0  = (blockIdx.x & 63) * 8;

    const float* Whh = dir ? Whh_b : Whh_f;
    const float* bhh = dir ? bhh_b : bhh_f;
    const float* xp  = dir ? g_xp_b : g_xp_f;
    float* ys        = dir ? g_ys_b : g_ys_f;

    ulonglong2 w[32];   // 128 floats = W_hh row tid, as 32x (2x f32x2)
    #pragma unroll
    for (int i = 0; i < 32; i++)
        w[i] = ((const ulonglong2*)(Whh + (long long)tid * 128))[i];
    const float bj = bhh[tid];

    if (tid < 128) {
        #pragma unroll
        for (int r = 0; r < 8; r++)
            hs[r * 128 + tid] = hidden[((long long)dir * BB + b0 + r) * HH + tid];
    }
    __syncthreads();

    const ulonglong2* h4 = (const ulonglong2*)hs;   // 32 per batch row

    for (int t = 0; t < TT; t++) {
        float xpv[8];
        const float* xpt = xp + ((long long)t * BB + b0) * G3 + tid;
        #pragma unroll
        for (int r = 0; r < 8; r++) xpv[r] = xpt[r * (long long)G3];

        ull acc2[8];
        #pragma unroll
        for (int r = 0; r < 8; r++) acc2[r] = 0ull;

        #pragma unroll
        for (int i = 0; i < 32; i++) {
            const ulonglong2 wi = w[i];
            #pragma unroll
            for (int r = 0; r < 8; r++) {
                const ulonglong2 hv = h4[r * 32 + i];
                dfma(acc2[r], wi.x, hv.x);
                dfma(acc2[r], wi.y, hv.y);
            }
        }

        float acc[8];
        #pragma unroll
        for (int r = 0; r < 8; r++) acc[r] = dsum(acc2[r]);

        if (tid < 256) {
            #pragma unroll
            for (int r = 0; r < 8; r++) {
                const float x = xpv[r] + acc[r] + bj;
                sg[tid * 9 + r] = __fdividef(1.f, 1.f + __expf(-x));
            }
        }
        __syncthreads();
        if (tid >= 256) {
            const int k = tid - 256;
            float* ysrow = ys + ((long long)t * BB + b0) * HH + k;
            #pragma unroll
            for (int r = 0; r < 8; r++) {
                const float rg = sg[k * 9 + r];
                const float zg = sg[(128 + k) * 9 + r];
                const float a  = xpv[r] + rg * (acc[r] + bj);
                const float e  = __expf(2.f * a);
                const float n  = 1.f - __fdividef(2.f, e + 1.f);
                const float ho = hs[r * 128 + k];
                const float hnew = (1.f - zg) * n + zg * ho;
                hs[r * 128 + k] = hnew;
                ysrow[r * (long long)HH] = hnew;
            }
        }
        __syncthreads();
    }
}

// ============================================================
// K3: hyp = tanh(f @ attn2_W^T + b) + ||f||^2. M=65536,N=256,K=256
// same k-pair FFMA2 scheme. fT2: 128 x 70 float2 ; Ws2: 64 x 134 float2
// ============================================================
#define X3_ROW 140
#define W3_ROW 268
#define X3_FLOATS (128 * X3_ROW)

__global__ __launch_bounds__(256) void k3_attn(
    const float* __restrict__ W, const float* __restrict__ bias)
{
    extern __shared__ float sm[];
    float* fTf = sm;                    // [128][X3_ROW]
    float* Wsf = sm + X3_FLOATS;        // [64][W3_ROW]

    const int tid  = threadIdx.x;
    const int row0 = blockIdx.x * 64;
    const int t    = row0 >> 9;
    const int b0   = row0 & 511;
    const int tb   = TT - 1 - t;
    const int coff = blockIdx.y * 128;

    {
        const int rg = tid >> 5, lane = tid & 31;
        for (int r = rg; r < 64; r += 8) {
            const float* yf = g_ys_f + ((long long)t * BB + b0 + r) * HH;
            const float* yb = g_ys_b + ((long long)tb * BB + b0 + r) * HH;
            for (int k = lane; k < HH; k += 32) {
                fTf[(k >> 1) * X3_ROW + r * 2 + (k & 1)] = yf[k];
                const int kb = k + HH;
                fTf[(kb >> 1) * X3_ROW + r * 2 + (kb & 1)] = yb[k];
            }
        }
    }
    __syncthreads();

    if (blockIdx.y == 0) {
        const int r = tid >> 2, q = tid & 3;
        float s = 0.f;
        #pragma unroll 8
        for (int k = q * 64; k < q * 64 + 64; k++) {
            const float v = fTf[(k >> 1) * X3_ROW + r * 2 + (k & 1)];
            s += v * v;
        }
        s += __shfl_xor_sync(0xffffffffu, s, 1);
        s += __shfl_xor_sync(0xffffffffu, s, 2);
        if (q == 0) g_rr2[row0 + r] = s;
    }

    ull acc2[4][8];
    #pragma unroll
    for (int i = 0; i < 4; i++)
        #pragma unroll
        for (int j = 0; j < 8; j++) acc2[i][j] = 0ull;

    const int tr = tid >> 4, tc = tid & 15;
    const ull* fTu = (const ull*)sm;
    const ulonglong2* Wsu = (const ulonglong2*)(sm + X3_FLOATS);

    for (int kc = 0; kc < 2; kc++) {
        __syncthreads();
        {
            const int cg = tid >> 5, lane = tid & 31;
            for (int c = cg; c < 128; c += 8) {
                const float* wrow = W + (long long)(coff + c) * DD + kc * 128;
                for (int k = lane; k < 128; k += 32)
                    Wsf[(k >> 1) * W3_ROW + c * 2 + (k & 1)] = wrow[k];
            }
        }
        __syncthreads();
        #pragma unroll 2
        for (int kk = 0; kk < 64; kk++) {
            ull av[4];
            const ull* xr = fTu + (kc * 64 + kk) * (X3_ROW / 2) + tr * 4;
            #pragma unroll
            for (int i = 0; i < 4; i++) av[i] = xr[i];
            ulonglong2 w0 = Wsu[kk * (W3_ROW / 4) + tc * 2];
            ulonglong2 w1 = Wsu[kk * (W3_ROW / 4) + tc * 2 + 1];
            ulonglong2 w2 = Wsu[kk * (W3_ROW / 4) + 32 + tc * 2];
            ulonglong2 w3 = Wsu[kk * (W3_ROW / 4) + 32 + tc * 2 + 1];
            ull wv[8] = {w0.x, w0.y, w1.x, w1.y, w2.x, w2.y, w3.x, w3.y};
            #pragma unroll
            for (int i = 0; i < 4; i++)
                #pragma unroll
                for (int j = 0; j < 8; j++)
                    dfma(acc2[i][j], av[i], wv[j]);
        }
    }

    #pragma unroll
    for (int j = 0; j < 8; j++) {
        const int c = coff + ((j < 4) ? (tc * 4 + j) : (64 + tc * 4 + (j - 4)));
        const float bv = bias[c];
        #pragma unroll
        for (int i = 0; i < 4; i++) {
            float v = dsum(acc2[i][j]) + bv;
            const float e = __expf(2.f * v);
            v = 1.f - __fdividef(2.f, e + 1.f);
            g_hyp[(long long)(row0 + tr * 4 + i) * DD + c] = v;
        }
    }
}

// ============================================================
// K4: hyperbolic scores, one warp per (t,b) row
// ============================================================
__global__ __launch_bounds__(256) void k4_scores(
    const float* __restrict__ cent, const float* __restrict__ beta)
{
    const int row  = blockIdx.x * 8 + (threadIdx.x >> 5);
    const int lane = threadIdx.x & 31;
    const float* hy = g_hyp + (long long)row * DD;

    float h2 = 0.f, cd = 0.f, c2 = 0.f;
    #pragma unroll
    for (int i = 0; i < 8; i++) {
        const float hv = hy[lane + 32 * i];
        const float cv = cent[lane + 32 * i];
        h2 += hv * hv; cd += hv * cv; c2 += cv * cv;
    }
    #pragma unroll
    for (int o = 16; o; o >>= 1) {
        h2 += __shfl_xor_sync(0xffffffffu, h2, o);
        cd += __shfl_xor_sync(0xffffffffu, cd, o);
        c2 += __shfl_xor_sync(0xffffffffu, c2, o);
    }
    if (lane == 0) {
        const float rh = sqrtf(h2), rc = sqrtf(c2);
        float pm = coshf(rh) * coshf(rc) - (sinhf(rh) / rh) * (sinhf(rc) / rc) * cd;
        pm = fminf(fmaxf(pm, 1.f + EPSF), 1e16f);
        const float dist = logf(pm) + log1pf(sqrtf(pm * pm - 1.f + EPSF) / pm);
        g_scores[row] = -beta[0] * dist - 1.f;
    }
}

// ============================================================
// K5: softmax x gamma Einstein-midpoint pooling + h_output
// ============================================================
__global__ __launch_bounds__(256) void k5_pool(float* __restrict__ out)
{
    __shared__ float wk[128];
    __shared__ float red[128];
    const int b = blockIdx.x, tid = threadIdx.x;

    float s = -1e30f;
    if (tid < 128) {
        s = g_scores[tid * BB + b];
        red[tid] = s;
    }
    __syncthreads();
    for (int o = 64; o; o >>= 1) {
        if (tid < o) red[tid] = fmaxf(red[tid], red[tid + o]);
        __syncthreads();
    }
    const float smax = red[0];
    __syncthreads();

    float myw = 0.f, kf = 0.f;
    if (tid < 128) {
        const float rr = sqrtf(g_rr2[tid * BB + b]);
        const float sh = sinhf(rr), ch = coshf(rr);
        const float th = sh / ch;
        float gsq = 1.f - th * th;
        gsq = fminf(fmaxf(gsq, EPSF), 1.f - EPSF);
        float gam = 1.f / sqrtf(gsq);
        gam = fminf(fmaxf(gam, 1.f + EPSF), 1e16f);
        myw = __expf(s - smax) * gam;
        kf = th / rr;
        red[tid] = myw;
    }
    __syncthreads();
    for (int o = 64; o; o >>= 1) {
        if (tid < o) red[tid] += red[tid + o];
        __syncthreads();
    }
    const float wsum = red[0];
    if (tid < 128) wk[tid] = (myw / wsum) * kf;
    __syncthreads();

    float acc = 0.f;
    if (tid < 128) {
        for (int t = 0; t < TT; t++)
            acc += wk[t] * g_ys_f[((long long)t * BB + b) * HH + tid];
    } else {
        const int k = tid - 128;
        for (int t = 0; t < TT; t++)
            acc += wk[t] * g_ys_b[((long long)(TT - 1 - t) * BB + b) * HH + k];
    }
    out[b * DD + tid] = acc;

    float* hout = out + BB * DD;
    if (tid < 128) {
        hout[b * HH + tid] = g_ys_f[((long long)(TT - 1) * BB + b) * HH + tid];
    } else {
        const int k = tid - 128;
        hout[BB * HH + b * HH + k] = g_ys_b[((long long)(TT - 1) * BB + b) * HH + k];
    }
}

// ============================================================
extern "C" void kernel_launch(void* const* d_in, const int* in_sizes, int n_in,
                              void* d_out, int out_size)
{
    const int*   tokens = (const int*)d_in[0];
    const float* hidden = (const float*)d_in[1];
    const float* emb    = (const float*)d_in[2];
    const float* W_ih_f = (const float*)d_in[3];
    const float* W_hh_f = (const float*)d_in[4];
    const float* b_ih_f = (const float*)d_in[5];
    const float* b_hh_f = (const float*)d_in[6];
    const float* W_ih_b = (const float*)d_in[7];
    const float* W_hh_b = (const float*)d_in[8];
    const float* b_ih_b = (const float*)d_in[9];
    const float* b_hh_b = (const float*)d_in[10];
    const float* attn2W = (const float*)d_in[11];
    const float* attn2b = (const float*)d_in[12];
    const float* cent   = (const float*)d_in[13];
    const float* beta   = (const float*)d_in[14];
    float* out = (float*)d_out;

    const int K1_SMEM = (X1_FLOATS + 50 * W1_ROW) * 4;   // 137,600 B
    const int K3_SMEM = (X3_FLOATS + 64 * W3_ROW) * 4;   // 140,288 B
    cudaFuncSetAttribute(k1_inproj, cudaFuncAttributeMaxDynamicSharedMemorySize, K1_SMEM);
    cudaFuncSetAttribute(k3_attn,   cudaFuncAttributeMaxDynamicSharedMemorySize, K3_SMEM);

    k1_inproj<<<dim3(1024, 6), 256, K1_SMEM>>>(tokens, emb, W_ih_f, b_ih_f, W_ih_b, b_ih_b);
    k2_scan<<<128, 384>>>(hidden, W_hh_f, b_hh_f, W_hh_b, b_hh_b);
    k3_attn<<<dim3(1024, 2), 256, K3_SMEM>>>(attn2W, attn2b);
    k4_scores<<<8192, 256>>>(cent, beta);
    k5_pool<<<512, 256>>>(out);
}

// round 6
// speedup vs baseline: 2.3876x; 2.3876x over previous
#include <cuda_runtime.h>
#include <math.h>

#define TT   128
#define BB   512
#define HH   128
#define EMBD 300
#define DD   256
#define G3   384
#define EPSF 1e-7f

typedef long long ll;

__device__ float g_xp_f[TT * BB * G3];
__device__ float g_xp_b[TT * BB * G3];
__device__ float g_ys_f[TT * BB * HH];
__device__ float g_ys_b[TT * BB * HH];
__device__ float g_hyp[TT * BB * DD];
__device__ float g_scores[TT * BB];
__device__ float g_rr2[TT * BB];

// ---- tf32 helpers ----
__device__ __forceinline__ unsigned f2tf32(float v) {
    unsigned u;
    asm("cvt.rna.tf32.f32 %0, %1;" : "=r"(u) : "f"(v));
    return u;
}
__device__ __forceinline__ void mma_tf32(float* c, const unsigned* a, const unsigned* b) {
    asm volatile(
        "mma.sync.aligned.m16n8k8.row.col.f32.tf32.tf32.f32 "
        "{%0,%1,%2,%3}, {%4,%5,%6,%7}, {%8,%9}, {%0,%1,%2,%3};"
        : "+f"(c[0]), "+f"(c[1]), "+f"(c[2]), "+f"(c[3])
        : "r"(a[0]), "r"(a[1]), "r"(a[2]), "r"(a[3]), "r"(b[0]), "r"(b[1]));
}

// Fragment-major smem layout, K staged in 64-wide slices (8 chunks of k8).
// A chunk: 8 mtiles * 32 lanes * 4 regs = 1024 floats, padded stride 1032.
// B chunk: 16 ntiles * 32 lanes * 2 regs = 1024 floats, padded stride 1032.
#define ACH 1032
#define BCH 1032
#define MMA_SMEM ((8 * ACH + 8 * BCH) * 4)   // 66,048 B

// A-frag m16n8k8 tf32: a0=(r,c) a1=(r+8,c) a2=(r,c+4) a3=(r+8,c+4)
__device__ __forceinline__ int a_off(int r, int kk) {   // r in [0,128), kk in [0,64)
    return (kk >> 3) * ACH + (r >> 4) * 128 + ((((r & 7) << 2) | (kk & 3)) << 2)
           + ((r >> 3) & 1) + (((kk >> 2) & 1) << 1);
}
// B-frag: b0=(k,c) b1=(k+4,c); lane=(c&7)<<2|(k&3)
__device__ __forceinline__ int b_off(int c, int kk) {   // c in [0,128), kk in [0,64)
    return (kk >> 3) * BCH + (c >> 3) * 64 + ((((c & 7) << 2) | (kk & 3)) << 1)
           + ((kk >> 2) & 1);
}

// ============================================================
// K1: embed gather + input projections via tf32 mma.
// M=65536, N=768 (6 col-blocks of 128), K=300 (pad 320, 5 slices)
// ============================================================
__global__ __launch_bounds__(256) void k1_mma(
    const int* __restrict__ tokens, const float* __restrict__ emb,
    const float* __restrict__ Wf, const float* __restrict__ bfv,
    const float* __restrict__ Wb, const float* __restrict__ bbv)
{
    extern __shared__ unsigned sm_u[];
    unsigned* As = sm_u;
    unsigned* Bs = sm_u + 8 * ACH;
    __shared__ int tk[128];

    const int tid  = threadIdx.x;
    const int lane = tid & 31;
    const int w    = tid >> 5;
    const int wm   = w >> 2;            // 0..1
    const int wn   = w & 3;             // 0..3
    const int row0 = blockIdx.x * 128;
    const int t    = row0 >> 9;
    const int b0   = row0 & 511;
    const int coff = blockIdx.y * 128;

    if (tid < 128) tk[tid] = tokens[row0 + tid];

    const bool fwd = (coff < G3);
    const float* Wsrc = fwd ? Wf : Wb;
    const float* bsrc = fwd ? bfv : bbv;
    const int cbase = fwd ? coff : (coff - G3);

    float acc[4][4][4];
    #pragma unroll
    for (int i = 0; i < 4; i++)
        #pragma unroll
        for (int j = 0; j < 4; j++)
            #pragma unroll
            for (int q = 0; q < 4; q++) acc[i][j][q] = 0.f;

    const int kk = tid & 63;
    const int rg = tid >> 6;

    for (int ks = 0; ks < 5; ks++) {
        const int kg = ks * 64 + kk;
        const bool kv = (kg < EMBD);
        __syncthreads();
        // stage A (embeddings, gathered)
        #pragma unroll 4
        for (int r = rg; r < 128; r += 4) {
            float v = kv ? emb[(ll)tk[r] * EMBD + kg] : 0.f;
            As[a_off(r, kk)] = f2tf32(v);
        }
        // stage B (weights)
        #pragma unroll 4
        for (int c = rg; c < 128; c += 4) {
            float v = kv ? Wsrc[(ll)(cbase + c) * EMBD + kg] : 0.f;
            Bs[b_off(c, kk)] = f2tf32(v);
        }
        __syncthreads();
        #pragma unroll
        for (int ck = 0; ck < 8; ck++) {
            unsigned a[4][4], b[4][2];
            #pragma unroll
            for (int i = 0; i < 4; i++) {
                uint4 av = *(const uint4*)(As + ck * ACH + (wm * 4 + i) * 128 + lane * 4);
                a[i][0] = av.x; a[i][1] = av.y; a[i][2] = av.z; a[i][3] = av.w;
            }
            #pragma unroll
            for (int j = 0; j < 4; j++) {
                uint2 bv = *(const uint2*)(Bs + ck * BCH + (wn * 4 + j) * 64 + lane * 2);
                b[j][0] = bv.x; b[j][1] = bv.y;
            }
            #pragma unroll
            for (int i = 0; i < 4; i++)
                #pragma unroll
                for (int j = 0; j < 4; j++)
                    mma_tf32(acc[i][j], a[i], b[j]);
        }
    }

    // epilogue: +bias, store to g_xp_f / g_xp_b (bwd pre-reversed in t)
    const int tb = TT - 1 - t;
    #pragma unroll
    for (int j = 0; j < 4; j++) {
        const int cl = cbase + wn * 32 + j * 8 + 2 * (lane & 3);
        const float bv0 = bsrc[cl], bv1 = bsrc[cl + 1];
        #pragma unroll
        for (int i = 0; i < 4; i++) {
            const int b_lo = b0 + wm * 64 + i * 16 + (lane >> 2);
            float2 vlo = make_float2(acc[i][j][0] + bv0, acc[i][j][1] + bv1);
            float2 vhi = make_float2(acc[i][j][2] + bv0, acc[i][j][3] + bv1);
            if (fwd) {
                *(float2*)&g_xp_f[((ll)t * BB + b_lo) * G3 + cl] = vlo;
                *(float2*)&g_xp_f[((ll)t * BB + b_lo + 8) * G3 + cl] = vhi;
            } else {
                *(float2*)&g_xp_b[((ll)tb * BB + b_lo) * G3 + cl] = vlo;
                *(float2*)&g_xp_b[((ll)tb * BB + b_lo + 8) * G3 + cl] = vhi;
            }
        }
    }
}

// ============================================================
// K2: GRU scan (fp32, round-2 form). 128 blocks x 384 thr.
// ============================================================
__global__ __launch_bounds__(384, 1) void k2_scan(
    const float* __restrict__ hidden,
    const float* __restrict__ Whh_f, const float* __restrict__ bhh_f,
    const float* __restrict__ Whh_b, const float* __restrict__ bhh_b)
{
    __shared__ __align__(16) float hs[8 * 128];
    __shared__ float sg[256 * 9];

    const int tid = threadIdx.x;
    const int dir = blockIdx.x >> 6;
    const int b0  = (blockIdx.x & 63) * 8;

    const float* Whh = dir ? Whh_b : Whh_f;
    const float* bhh = dir ? bhh_b : bhh_f;
    const float* xp  = dir ? g_xp_b : g_xp_f;
    float* ys        = dir ? g_ys_b : g_ys_f;

    float4 w[32];
    #pragma unroll
    for (int i = 0; i < 32; i++)
        w[i] = *(const float4*)&Whh[tid * 128 + i * 4];
    const float bj = bhh[tid];

    if (tid < 128) {
        #pragma unroll
        for (int r = 0; r < 8; r++)
            hs[r * 128 + tid] = hidden[((ll)dir * BB + b0 + r) * HH + tid];
    }
    __syncthreads();

    const float4* h4 = (const float4*)hs;

    for (int t = 0; t < TT; t++) {
        float xpv[8];
        const float* xpt = xp + ((ll)t * BB + b0) * G3 + tid;
        #pragma unroll
        for (int r = 0; r < 8; r++) xpv[r] = xpt[r * (ll)G3];

        float acc[8];
        #pragma unroll
        for (int r = 0; r < 8; r++) acc[r] = 0.f;

        #pragma unroll
        for (int i = 0; i < 32; i++) {
            const float4 wi = w[i];
            #pragma unroll
            for (int r = 0; r < 8; r++) {
                const float4 hv = h4[r * 32 + i];
                acc[r] += wi.x * hv.x + wi.y * hv.y + wi.z * hv.z + wi.w * hv.w;
            }
        }

        if (tid < 256) {
            #pragma unroll
            for (int r = 0; r < 8; r++) {
                const float x = xpv[r] + acc[r] + bj;
                sg[tid * 9 + r] = __fdividef(1.f, 1.f + __expf(-x));
            }
        }
        __syncthreads();
        if (tid >= 256) {
            const int k = tid - 256;
            float* ysrow = ys + ((ll)t * BB + b0) * HH + k;
            #pragma unroll
            for (int r = 0; r < 8; r++) {
                const float rg = sg[k * 9 + r];
                const float zg = sg[(128 + k) * 9 + r];
                const float a  = xpv[r] + rg * (acc[r] + bj);
                const float e  = __expf(2.f * a);
                const float n  = 1.f - __fdividef(2.f, e + 1.f);
                const float ho = hs[r * 128 + k];
                const float hnew = (1.f - zg) * n + zg * ho;
                hs[r * 128 + k] = hnew;
                ysrow[r * (ll)HH] = hnew;
            }
        }
        __syncthreads();
    }
}

// ============================================================
// K3: hyp = tanh(f @ attn2_W^T + b) via tf32 mma.
// M=65536, N=256 (2 col-blocks), K=256 (4 slices of 64)
// ============================================================
__global__ __launch_bounds__(256) void k3_mma(
    const float* __restrict__ W, const float* __restrict__ bias)
{
    extern __shared__ unsigned sm_u[];
    unsigned* As = sm_u;
    unsigned* Bs = sm_u + 8 * ACH;

    const int tid  = threadIdx.x;
    const int lane = tid & 31;
    const int w    = tid >> 5;
    const int wm   = w >> 2;
    const int wn   = w & 3;
    const int row0 = blockIdx.x * 128;
    const int t    = row0 >> 9;
    const int b0   = row0 & 511;
    const int tb   = TT - 1 - t;
    const int coff = blockIdx.y * 128;

    float acc[4][4][4];
    #pragma unroll
    for (int i = 0; i < 4; i++)
        #pragma unroll
        for (int j = 0; j < 4; j++)
            #pragma unroll
            for (int q = 0; q < 4; q++) acc[i][j][q] = 0.f;

    const int kk = tid & 63;
    const int rg = tid >> 6;

    for (int ks = 0; ks < 4; ks++) {
        const int kg = ks * 64 + kk;
        __syncthreads();
        // stage A: f_output = [ys_f[t] | ys_b[T-1-t]]
        #pragma unroll 4
        for (int r = rg; r < 128; r += 4) {
            const int b = b0 + r;
            float v = (kg < HH)
                ? g_ys_f[((ll)t * BB + b) * HH + kg]
                : g_ys_b[((ll)tb * BB + b) * HH + (kg - HH)];
            As[a_off(r, kk)] = f2tf32(v);
        }
        // stage B
        #pragma unroll 4
        for (int c = rg; c < 128; c += 4) {
            float v = W[(ll)(coff + c) * DD + kg];
            Bs[b_off(c, kk)] = f2tf32(v);
        }
        __syncthreads();
        #pragma unroll
        for (int ck = 0; ck < 8; ck++) {
            unsigned a[4][4], b[4][2];
            #pragma unroll
            for (int i = 0; i < 4; i++) {
                uint4 av = *(const uint4*)(As + ck * ACH + (wm * 4 + i) * 128 + lane * 4);
                a[i][0] = av.x; a[i][1] = av.y; a[i][2] = av.z; a[i][3] = av.w;
            }
            #pragma unroll
            for (int j = 0; j < 4; j++) {
                uint2 bv = *(const uint2*)(Bs + ck * BCH + (wn * 4 + j) * 64 + lane * 2);
                b[j][0] = bv.x; b[j][1] = bv.y;
            }
            #pragma unroll
            for (int i = 0; i < 4; i++)
                #pragma unroll
                for (int j = 0; j < 4; j++)
                    mma_tf32(acc[i][j], a[i], b[j]);
        }
    }

    #pragma unroll
    for (int j = 0; j < 4; j++) {
        const int n = coff + wn * 32 + j * 8 + 2 * (lane & 3);
        const float bv0 = bias[n], bv1 = bias[n + 1];
        #pragma unroll
        for (int i = 0; i < 4; i++) {
            const int m_lo = row0 + wm * 64 + i * 16 + (lane >> 2);
            float v[4] = {acc[i][j][0] + bv0, acc[i][j][1] + bv1,
                          acc[i][j][2] + bv0, acc[i][j][3] + bv1};
            #pragma unroll
            for (int q = 0; q < 4; q++) {
                const float e = __expf(2.f * v[q]);
                v[q] = 1.f - __fdividef(2.f, e + 1.f);
            }
            *(float2*)&g_hyp[(ll)m_lo * DD + n] = make_float2(v[0], v[1]);
            *(float2*)&g_hyp[(ll)(m_lo + 8) * DD + n] = make_float2(v[2], v[3]);
        }
    }
}

// ============================================================
// K3b: ||f_output||^2 per (t,b), warp per row
// ============================================================
__global__ __launch_bounds__(256) void k3b_rr2()
{
    const int row  = blockIdx.x * 8 + (threadIdx.x >> 5);
    const int lane = threadIdx.x & 31;
    const int t = row >> 9, b = row & 511;
    const float* yf = g_ys_f + ((ll)t * BB + b) * HH;
    const float* yb = g_ys_b + ((ll)(TT - 1 - t) * BB + b) * HH;

    float s = 0.f;
    #pragma unroll
    for (int i = 0; i < 4; i++) {
        const float a = yf[lane + 32 * i];
        const float c = yb[lane + 32 * i];
        s += a * a + c * c;
    }
    #pragma unroll
    for (int o = 16; o; o >>= 1) s += __shfl_xor_sync(0xffffffffu, s, o);
    if (lane == 0) g_rr2[row] = s;
}

// ============================================================
// K4: hyperbolic scores, one warp per (t,b) row
// ============================================================
__global__ __launch_bounds__(256) void k4_scores(
    const float* __restrict__ cent, const float* __restrict__ beta)
{
    const int row  = blockIdx.x * 8 + (threadIdx.x >> 5);
    const int lane = threadIdx.x & 31;
    const float* hy = g_hyp + (ll)row * DD;

    float h2 = 0.f, cd = 0.f, c2 = 0.f;
    #pragma unroll
    for (int i = 0; i < 8; i++) {
        const float hv = hy[lane + 32 * i];
        const float cv = cent[lane + 32 * i];
        h2 += hv * hv; cd += hv * cv; c2 += cv * cv;
    }
    #pragma unroll
    for (int o = 16; o; o >>= 1) {
        h2 += __shfl_xor_sync(0xffffffffu, h2, o);
        cd += __shfl_xor_sync(0xffffffffu, cd, o);
        c2 += __shfl_xor_sync(0xffffffffu, c2, o);
    }
    if (lane == 0) {
        const float rh = sqrtf(h2), rc = sqrtf(c2);
        float pm = coshf(rh) * coshf(rc) - (sinhf(rh) / rh) * (sinhf(rc) / rc) * cd;
        pm = fminf(fmaxf(pm, 1.f + EPSF), 1e16f);
        const float dist = logf(pm) + log1pf(sqrtf(pm * pm - 1.f + EPSF) / pm);
        g_scores[row] = -beta[0] * dist - 1.f;
    }
}

// ============================================================
// K5: softmax x gamma Einstein-midpoint pooling + h_output
// ============================================================
__global__ __launch_bounds__(256) void k5_pool(float* __restrict__ out)
{
    __shared__ float wk[128];
    __shared__ float red[128];
    const int b = blockIdx.x, tid = threadIdx.x;

    float s = -1e30f;
    if (tid < 128) {
        s = g_scores[tid * BB + b];
        red[tid] = s;
    }
    __syncthreads();
    for (int o = 64; o; o >>= 1) {
        if (tid < o) red[tid] = fmaxf(red[tid], red[tid + o]);
        __syncthreads();
    }
    const float smax = red[0];
    __syncthreads();

    float myw = 0.f, kf = 0.f;
    if (tid < 128) {
        const float rr = sqrtf(g_rr2[tid * BB + b]);
        const float sh = sinhf(rr), ch = coshf(rr);
        const float th = sh / ch;
        float gsq = 1.f - th * th;
        gsq = fminf(fmaxf(gsq, EPSF), 1.f - EPSF);
        float gam = 1.f / sqrtf(gsq);
        gam = fminf(fmaxf(gam, 1.f + EPSF), 1e16f);
        myw = __expf(s - smax) * gam;
        kf = th / rr;
        red[tid] = myw;
    }
    __syncthreads();
    for (int o = 64; o; o >>= 1) {
        if (tid < o) red[tid] += red[tid + o];
        __syncthreads();
    }
    const float wsum = red[0];
    if (tid < 128) wk[tid] = (myw / wsum) * kf;
    __syncthreads();

    float acc = 0.f;
    if (tid < 128) {
        for (int t = 0; t < TT; t++)
            acc += wk[t] * g_ys_f[((ll)t * BB + b) * HH + tid];
    } else {
        const int k = tid - 128;
        for (int t = 0; t < TT; t++)
            acc += wk[t] * g_ys_b[((ll)(TT - 1 - t) * BB + b) * HH + k];
    }
    out[b * DD + tid] = acc;

    float* hout = out + BB * DD;
    if (tid < 128) {
        hout[b * HH + tid] = g_ys_f[((ll)(TT - 1) * BB + b) * HH + tid];
    } else {
        const int k = tid - 128;
        hout[BB * HH + b * HH + k] = g_ys_b[((ll)(TT - 1) * BB + b) * HH + k];
    }
}

// ============================================================
extern "C" void kernel_launch(void* const* d_in, const int* in_sizes, int n_in,
                              void* d_out, int out_size)
{
    const int*   tokens = (const int*)d_in[0];
    const float* hidden = (const float*)d_in[1];
    const float* emb    = (const float*)d_in[2];
    const float* W_ih_f = (const float*)d_in[3];
    const float* W_hh_f = (const float*)d_in[4];
    const float* b_ih_f = (const float*)d_in[5];
    const float* b_hh_f = (const float*)d_in[6];
    const float* W_ih_b = (const float*)d_in[7];
    const float* W_hh_b = (const float*)d_in[8];
    const float* b_ih_b = (const float*)d_in[9];
    const float* b_hh_b = (const float*)d_in[10];
    const float* attn2W = (const float*)d_in[11];
    const float* attn2b = (const float*)d_in[12];
    const float* cent   = (const float*)d_in[13];
    const float* beta   = (const float*)d_in[14];
    float* out = (float*)d_out;

    cudaFuncSetAttribute(k1_mma, cudaFuncAttributeMaxDynamicSharedMemorySize, MMA_SMEM);
    cudaFuncSetAttribute(k3_mma, cudaFuncAttributeMaxDynamicSharedMemorySize, MMA_SMEM);

    k1_mma<<<dim3(512, 6), 256, MMA_SMEM>>>(tokens, emb, W_ih_f, b_ih_f, W_ih_b, b_ih_b);
    k2_scan<<<128, 384>>>(hidden, W_hh_f, b_hh_f, W_hh_b, b_hh_b);
    k3_mma<<<dim3(512, 2), 256, MMA_SMEM>>>(attn2W, attn2b);
    k3b_rr2<<<8192, 256>>>();
    k4_scores<<<8192, 256>>>(cent, beta);
    k5_pool<<<512, 256>>>(out);
}